// round 7
// baseline (speedup 1.0000x reference)
#include <cuda_runtime.h>
#include <cuda_fp16.h>
#include <math.h>

// Problem constants
#define CTRLN 256
#define WORDN 128
#define MEMN  128
#define DINN  64
#define BN    512
#define TN    512
#define GINN  192            // D_IN + WORD
#define EPSF  1e-6f

// ---------------- device scratch (static, no allocs) ----------------
__device__ __half g_WIH[24 * 768 * 8];    // [k8][o(768)][p(8)] halves, k = 8*k8+p
__device__ __half g_WHH[32 * 768 * 8];
__device__ __half g_WHD[32 * 512 * 8];    // head: key|erase|add|beta|pad

// ---------------- helpers ----------------
__device__ __forceinline__ void ffma2(float2 &d, float2 a, float2 b) {
    unsigned long long &du = reinterpret_cast<unsigned long long &>(d);
    unsigned long long au = reinterpret_cast<unsigned long long &>(a);
    unsigned long long bu = reinterpret_cast<unsigned long long &>(b);
    asm("fma.rn.f32x2 %0, %1, %2, %0;" : "+l"(du) : "l"(au), "l"(bu));
}
__device__ __forceinline__ float2 dup2(float a) { return make_float2(a, a); }
__device__ __forceinline__ float sigf(float x) { return 1.0f / (1.0f + __expf(-x)); }
__device__ __forceinline__ float softplusf(float x) {
    return fmaxf(x, 0.0f) + log1pf(__expf(-fabsf(x)));
}
#define BARN(id, cnt) asm volatile("bar.sync %0, %1;" :: "r"(id), "r"(cnt) : "memory")

// ---------------- K0: weight repack to fp16 ----------------
__global__ void ntm_prep(const float* __restrict__ W_ih, const float* __restrict__ W_hh,
                         const float* __restrict__ W_key, const float* __restrict__ W_beta,
                         const float* __restrict__ W_erase, const float* __restrict__ W_add) {
    int stride = gridDim.x * blockDim.x;
    int idx0 = blockIdx.x * blockDim.x + threadIdx.x;
    for (int i = idx0; i < 768 * 192; i += stride) {
        int o = i / 192, k = i % 192;
        g_WIH[((k >> 3) * 768 + o) * 8 + (k & 7)] = __float2half(W_ih[i]);
    }
    for (int i = idx0; i < 768 * 256; i += stride) {
        int o = i / 256, k = i % 256;
        g_WHH[((k >> 3) * 768 + o) * 8 + (k & 7)] = __float2half(W_hh[i]);
    }
    for (int i = idx0; i < 32 * 512 * 8; i += stride) {
        int k8 = i / (512 * 8);
        int r = i % (512 * 8);
        int o = r >> 3, p = r & 7;
        int k = k8 * 8 + p;
        float v = 0.0f;
        if (o < 128)       v = W_key[o * 256 + k];
        else if (o < 256)  v = W_erase[(o - 128) * 256 + k];
        else if (o < 384)  v = W_add[(o - 256) * 256 + k];
        else if (o == 384) v = W_beta[k];
        g_WHD[i] = __float2half(v);
    }
}

// ---------------- GEMV partial: 3-gate rows j/256+j/512+j over k8 range ----------------
__device__ __forceinline__ void gemv_part(const __half* Wbase, int k8beg, int k8end,
                                          const float (*src)[4], int j,
                                          float2 &r0, float2 &r1, float2 &z0, float2 &z1,
                                          float2 &n0, float2 &n1) {
    const uint4* W = (const uint4*)Wbase;
    #pragma unroll 4
    for (int k8 = k8beg; k8 < k8end; ++k8) {
        uint4 uwr = __ldg(&W[k8 * 768 + j]);
        uint4 uwz = __ldg(&W[k8 * 768 + 256 + j]);
        uint4 uwn = __ldg(&W[k8 * 768 + 512 + j]);
        const __half2* hr = (const __half2*)&uwr;
        const __half2* hz = (const __half2*)&uwz;
        const __half2* hn = (const __half2*)&uwn;
        #pragma unroll
        for (int q = 0; q < 4; ++q) {
            float2 wr2 = __half22float2(hr[q]);
            float2 wz2 = __half22float2(hz[q]);
            float2 wn2 = __half22float2(hn[q]);
            float4 ia = *(const float4*)&src[k8 * 8 + 2 * q][0];
            float4 ib = *(const float4*)&src[k8 * 8 + 2 * q + 1][0];
            float2 a01 = make_float2(ia.x, ia.y), a23 = make_float2(ia.z, ia.w);
            float2 b01 = make_float2(ib.x, ib.y), b23 = make_float2(ib.z, ib.w);
            ffma2(r0, dup2(wr2.x), a01); ffma2(r1, dup2(wr2.x), a23);
            ffma2(z0, dup2(wz2.x), a01); ffma2(z1, dup2(wz2.x), a23);
            ffma2(n0, dup2(wn2.x), a01); ffma2(n1, dup2(wn2.x), a23);
            ffma2(r0, dup2(wr2.y), b01); ffma2(r1, dup2(wr2.y), b23);
            ffma2(z0, dup2(wz2.y), b01); ffma2(z1, dup2(wz2.y), b23);
            ffma2(n0, dup2(wn2.y), b01); ffma2(n1, dup2(wn2.y), b23);
        }
    }
}

// gh + gi_x split-K: part 0 -> WIH k8 0..8 (ai) + WHH k8 0..12 (ah), seeds biases
//                    part 1 -> WHH k8 12..32 (ah), zero-seeded
__device__ __forceinline__ void gemv_P2(int j, int part,
                                        float bR, float bZ, float bNi, float bNh,
                                        const float (*s_in)[4], const float (*s_h)[4],
                                        float (*red)[256]) {
    float2 ar0, ar1, az0, az1, ai0, ai1, ah0, ah1;
    if (part == 0) {
        ar0 = dup2(bR); ar1 = dup2(bR);
        az0 = dup2(bZ); az1 = dup2(bZ);
        ai0 = dup2(bNi); ai1 = dup2(bNi);
        ah0 = dup2(bNh); ah1 = dup2(bNh);
        gemv_part(g_WIH, 0, 8, s_in, j, ar0, ar1, az0, az1, ai0, ai1);
        gemv_part(g_WHH, 0, 12, s_h, j, ar0, ar1, az0, az1, ah0, ah1);
    } else {
        ar0 = make_float2(0.f, 0.f); ar1 = ar0; az0 = ar0; az1 = ar0;
        ai0 = ar0; ai1 = ar0; ah0 = ar0; ah1 = ar0;
        gemv_part(g_WHH, 12, 32, s_h, j, ar0, ar1, az0, az1, ah0, ah1);
    }
    red[0][j] = ar0.x;  red[1][j] = ar0.y;  red[2][j] = ar1.x;  red[3][j] = ar1.y;
    red[4][j] = az0.x;  red[5][j] = az0.y;  red[6][j] = az1.x;  red[7][j] = az1.y;
    red[8][j] = ai0.x;  red[9][j] = ai0.y;  red[10][j] = ai1.x; red[11][j] = ai1.y;
    red[12][j] = ah0.x; red[13][j] = ah0.y; red[14][j] = ah1.x; red[15][j] = ah1.y;
}

#define SMEM_TOTAL 195648

// ---------------- K1: persistent pipelined kernel, 768 threads ----------------
__global__ __launch_bounds__(768, 1)
void ntm_main(const float* __restrict__ data, const int* __restrict__ batch_sizes,
              const int* __restrict__ unsort_idxs,
              const float* __restrict__ b_ih, const float* __restrict__ b_hh,
              const float* __restrict__ b_key, const float* __restrict__ b_beta,
              const float* __restrict__ b_erase, const float* __restrict__ b_add,
              const float* __restrict__ M0, float* __restrict__ out) {
    extern __shared__ __align__(16) unsigned char dsm[];
    float (*s_in)[4]        = (float(*)[4])(dsm);              // [192][4]
    float (*s_h)[4]         = (float(*)[4])(dsm + 3072);       // [256][4]
    float (*s_gi)[4]        = (float(*)[4])(dsm + 7168);       // [768][4] gi_read per output
    float (*s_redB1)[256]   = (float(*)[256])(dsm + 19456);    // [16][256]
    float (*s_redB2)[256]   = (float(*)[256])(dsm + 35840);    // [16][256]
    float (*s_key)[128]     = (float(*)[128])(dsm + 52224);    // [4][128]
    float (*s_e)[128]       = (float(*)[128])(dsm + 54272);
    float (*s_a)[128]       = (float(*)[128])(dsm + 56320);
    float (*s_w)[128]       = (float(*)[128])(dsm + 58368);
    float (*s_racc)[2][128] = (float(*)[2][128])(dsm + 60416); // [4][2][128]
    float* s_beta           = (float*)(dsm + 64512);
    int*   s_len            = (int*)(dsm + 64528);
    int*   s_dst            = (int*)(dsm + 64544);
    __half* s_M             = (__half*)(dsm + 64576);          // [4][128][128] fp16

    const int tid = threadIdx.x;
    const int lane = tid & 31;
    const int warp = tid >> 5;
    const int b0 = blockIdx.x * 4;
    const int j = tid & 255;
    const int g = tid >> 8;      // 0 = MEM (warps 0-7), 1/2 = GEMV split-K halves

    // ---- active lengths ----
    if (warp < 4) {
        int e = warp, cnt = 0;
        for (int t = lane; t < TN; t += 32) cnt += (batch_sizes[t] > (b0 + e)) ? 1 : 0;
        #pragma unroll
        for (int s = 16; s; s >>= 1) cnt += __shfl_xor_sync(0xffffffffu, cnt, s);
        if (lane == 0) s_len[e] = cnt;
    }
    // ---- init M in SMEM from M0 (fp32 -> fp16), 4 copies ----
    for (int i = tid; i < (MEMN * WORDN) / 2; i += 768) {
        float2 f = ((const float2*)M0)[i];
        __half2 h = __floats2half2_rn(f.x, f.y);
        #pragma unroll
        for (int e = 0; e < 4; e++)
            ((__half2*)s_M)[e * ((MEMN * WORDN) / 2) + i] = h;
    }
    for (int i = tid; i < GINN * 4; i += 768) (&s_in[0][0])[i] = 0.0f;
    for (int i = tid; i < CTRLN * 4; i += 768) (&s_h[0][0])[i] = 0.0f;

    // ---- biases ----
    float bR = 0.f, bZ = 0.f, bNi = 0.f, bNh = 0.f;   // GEMV part0 threads
    if (g == 1) {
        bR = b_ih[j] + b_hh[j];
        bZ = b_ih[256 + j] + b_hh[256 + j];
        bNi = b_ih[512 + j];
        bNh = b_hh[512 + j];
    }
    float bH1 = 0.f, bH2 = 0.f;                       // MEM threads (head outputs j, 256+j)
    if (g == 0) {
        bH1 = (j < 128) ? b_key[j] : b_erase[j - 128];
        bH2 = (j < 128) ? b_add[j] : ((j == 128) ? b_beta[0] : 0.0f);
    }

    // ---- x prefetch prologue (MEM threads) ----
    const int xe = j >> 6, xd = j & 63;
    float xreg = 0.f;
    if (g == 0) xreg = data[((size_t)0 * BN + (b0 + xe)) * DINN + xd];   // x_0
    __syncthreads();

    const int L0 = s_len[0], L1 = s_len[1], L2 = s_len[2], L3 = s_len[3];
    const int Tmax = max(max(L0, L1), max(L2, L3));

    if (g == 0) {
        s_in[xd][xe] = xreg;                                             // x_0 -> smem
        xreg = data[((size_t)1 * BN + (b0 + xe)) * DINN + xd];           // x_1 -> reg
    }
    __syncthreads();
    // prologue pipelined GEMV: P_0 = gh(h=0) + gi_x(x_0) + biases
    if (g == 1) gemv_P2(j, 0, bR, bZ, bNi, bNh, s_in, s_h, s_redB1);
    if (g == 2) gemv_P2(j, 1, bR, bZ, bNi, bNh, s_in, s_h, s_redB2);
    __syncthreads();

    for (int t = 0; t < Tmax; ++t) {
        // ============ SERIAL: gi_read by output (768 threads, 1 output each) ============
        {
            float2 a01 = make_float2(0.f, 0.f), a23 = make_float2(0.f, 0.f);
            const uint4* W = (const uint4*)g_WIH;
            #pragma unroll 4
            for (int k8 = 8; k8 < 24; ++k8) {
                uint4 uw = __ldg(&W[k8 * 768 + tid]);
                const __half2* hw = (const __half2*)&uw;
                #pragma unroll
                for (int q = 0; q < 4; ++q) {
                    float2 w2 = __half22float2(hw[q]);
                    float4 ia = *(const float4*)&s_in[k8 * 8 + 2 * q][0];
                    float4 ib = *(const float4*)&s_in[k8 * 8 + 2 * q + 1][0];
                    ffma2(a01, dup2(w2.x), make_float2(ia.x, ia.y));
                    ffma2(a23, dup2(w2.x), make_float2(ia.z, ia.w));
                    ffma2(a01, dup2(w2.y), make_float2(ib.x, ib.y));
                    ffma2(a23, dup2(w2.y), make_float2(ib.z, ib.w));
                }
            }
            *(float4*)&s_gi[tid][0] = make_float4(a01.x, a01.y, a23.x, a23.y);
        }
        __syncthreads();   // B1

        // ---- combine + gates + x-store (MEM threads) ----
        if (g == 0) {
            float4 gr = *(const float4*)&s_gi[j][0];
            float4 gz = *(const float4*)&s_gi[256 + j][0];
            float4 gn = *(const float4*)&s_gi[512 + j][0];
            float prv[4] = {gr.x, gr.y, gr.z, gr.w};
            float pzv[4] = {gz.x, gz.y, gz.z, gz.w};
            float piv[4] = {gn.x, gn.y, gn.z, gn.w};
            float4 hold = *(const float4*)&s_h[j][0];
            float ho[4] = {hold.x, hold.y, hold.z, hold.w};
            float hn_[4];
            #pragma unroll
            for (int e = 0; e < 4; e++) {
                float ppr = prv[e] + s_redB1[e][j] + s_redB2[e][j];
                float ppz = pzv[e] + s_redB1[4 + e][j] + s_redB2[4 + e][j];
                float ppi = piv[e] + s_redB1[8 + e][j] + s_redB2[8 + e][j];
                float pph = s_redB1[12 + e][j] + s_redB2[12 + e][j];
                float r = sigf(ppr);
                float z = sigf(ppz);
                float n = tanhf(ppi + r * pph);
                hn_[e] = (1.0f - z) * n + z * ho[e];
            }
            if (t < L0) s_h[j][0] = hn_[0];
            if (t < L1) s_h[j][1] = hn_[1];
            if (t < L2) s_h[j][2] = hn_[2];
            if (t < L3) s_h[j][3] = hn_[3];
            // x_{t+1} -> smem, prefetch x_{t+2}
            s_in[xd][xe] = xreg;
            int tn = min(t + 2, TN - 1);
            xreg = data[((size_t)tn * BN + (b0 + xe)) * DINN + xd];
        }
        __syncthreads();   // B2: h_t and x_{t+1} ready

        // ============ PARALLEL SEGMENT ============
        if (g == 1) {
            gemv_P2(j, 0, bR, bZ, bNi, bNh, s_in, s_h, s_redB1);
        } else if (g == 2) {
            gemv_P2(j, 1, bR, bZ, bNi, bNh, s_in, s_h, s_redB2);
        } else {
            // ---- MEM: head GEMV (outputs j, 256+j; K=256) ----
            float2 h10 = dup2(bH1), h11 = dup2(bH1);
            float2 h20 = dup2(bH2), h21 = dup2(bH2);
            {
                const uint4* W = (const uint4*)g_WHD;
                #pragma unroll 4
                for (int k8 = 0; k8 < 32; ++k8) {
                    uint4 uw1 = __ldg(&W[k8 * 512 + j]);
                    uint4 uw2 = __ldg(&W[k8 * 512 + 256 + j]);
                    const __half2* h1p = (const __half2*)&uw1;
                    const __half2* h2p = (const __half2*)&uw2;
                    #pragma unroll
                    for (int q = 0; q < 4; ++q) {
                        float2 w12 = __half22float2(h1p[q]);
                        float2 w22 = __half22float2(h2p[q]);
                        float4 ia = *(const float4*)&s_h[k8 * 8 + 2 * q][0];
                        float4 ib = *(const float4*)&s_h[k8 * 8 + 2 * q + 1][0];
                        float2 a01 = make_float2(ia.x, ia.y), a23 = make_float2(ia.z, ia.w);
                        float2 b01 = make_float2(ib.x, ib.y), b23 = make_float2(ib.z, ib.w);
                        ffma2(h10, dup2(w12.x), a01); ffma2(h11, dup2(w12.x), a23);
                        ffma2(h20, dup2(w22.x), a01); ffma2(h21, dup2(w22.x), a23);
                        ffma2(h10, dup2(w12.y), b01); ffma2(h11, dup2(w12.y), b23);
                        ffma2(h20, dup2(w22.y), b01); ffma2(h21, dup2(w22.y), b23);
                    }
                }
            }
            {
                float v1[4] = {h10.x, h10.y, h11.x, h11.y};
                float v2[4] = {h20.x, h20.y, h21.x, h21.y};
                #pragma unroll
                for (int e = 0; e < 4; e++) {
                    if (j < 128) {
                        s_key[e][j] = tanhf(v1[e]);   // raw key
                        s_a[e][j] = v2[e];
                    } else {
                        s_e[e][j - 128] = sigf(v1[e]);
                        if (j == 128) s_beta[e] = softplusf(v2[e]);
                    }
                }
            }
            BARN(5, 256);   // all head outputs visible to all MEM warps

            const int e = warp >> 1, half = warp & 1;
            const int Le = s_len[e];
            if (t < Le) {
                // ---- pass 1: dot(M, k_raw)/(||M||+eps), M from SMEM ----
                const __half* Me = s_M + e * (MEMN * WORDN);
                {
                    int rl = lane >> 3;
                    int cc = (lane & 7) * 16;
                    float2 kx[8];
                    #pragma unroll
                    for (int i = 0; i < 8; i++)
                        kx[i] = make_float2(s_key[e][cc + 2 * i], s_key[e][cc + 2 * i + 1]);
                    #pragma unroll 4
                    for (int mb = half * 64; mb < half * 64 + 64; mb += 4) {
                        int m = mb + rl;
                        const uint4* Mr = (const uint4*)(Me + m * WORDN + cc);
                        uint4 u0 = Mr[0];
                        uint4 u1 = Mr[1];
                        const __half2* p0 = (const __half2*)&u0;
                        const __half2* p1 = (const __half2*)&u1;
                        float2 d2 = make_float2(0.f, 0.f), n2 = make_float2(0.f, 0.f);
                        #pragma unroll
                        for (int q = 0; q < 4; q++) {
                            float2 f0 = __half22float2(p0[q]);
                            float2 f1 = __half22float2(p1[q]);
                            ffma2(d2, f0, kx[q]);
                            ffma2(n2, f0, f0);
                            ffma2(d2, f1, kx[4 + q]);
                            ffma2(n2, f1, f1);
                        }
                        float dot = d2.x + d2.y, nrm = n2.x + n2.y;
                        #pragma unroll
                        for (int s = 1; s < 8; s <<= 1) {
                            dot += __shfl_xor_sync(0xffffffffu, dot, s);
                            nrm += __shfl_xor_sync(0xffffffffu, nrm, s);
                        }
                        if ((lane & 7) == 0) s_w[e][m] = dot / (sqrtf(nrm) + EPSF);
                    }
                }
                BARN(1 + e, 64);
                // ---- softmax (half==0 warp): scale = beta / (||k||+eps) ----
                if (half == 0) {
                    float q0 = s_key[e][lane];
                    float q1 = s_key[e][lane + 32];
                    float q2 = s_key[e][lane + 64];
                    float q3 = s_key[e][lane + 96];
                    float ss = q0 * q0 + q1 * q1 + q2 * q2 + q3 * q3;
                    #pragma unroll
                    for (int s = 16; s; s >>= 1) ss += __shfl_xor_sync(0xffffffffu, ss, s);
                    float scale = s_beta[e] / (sqrtf(ss) + EPSF);
                    float v0 = scale * s_w[e][lane];
                    float v1 = scale * s_w[e][lane + 32];
                    float v2 = scale * s_w[e][lane + 64];
                    float v3 = scale * s_w[e][lane + 96];
                    float mx = fmaxf(fmaxf(v0, v1), fmaxf(v2, v3));
                    #pragma unroll
                    for (int s = 16; s; s >>= 1) mx = fmaxf(mx, __shfl_xor_sync(0xffffffffu, mx, s));
                    v0 = __expf(v0 - mx); v1 = __expf(v1 - mx);
                    v2 = __expf(v2 - mx); v3 = __expf(v3 - mx);
                    float sum = v0 + v1 + v2 + v3;
                    #pragma unroll
                    for (int s = 16; s; s >>= 1) sum += __shfl_xor_sync(0xffffffffu, sum, s);
                    float inv = 1.0f / sum;
                    s_w[e][lane] = v0 * inv;
                    s_w[e][lane + 32] = v1 * inv;
                    s_w[e][lane + 64] = v2 * inv;
                    s_w[e][lane + 96] = v3 * inv;
                }
                BARN(1 + e, 64);
                // ---- pass 2: read + M update, all in SMEM, f32x2 math ----
                {
                    __half* Mw = s_M + e * (MEMN * WORDN) + lane * 4;
                    float4 e4 = *(const float4*)&s_e[e][lane * 4];
                    float4 a4 = *(const float4*)&s_a[e][lane * 4];
                    float2 e01 = make_float2(-e4.x, -e4.y), e23 = make_float2(-e4.z, -e4.w);
                    float2 a01 = make_float2(a4.x, a4.y),   a23 = make_float2(a4.z, a4.w);
                    float2 r01 = make_float2(0.f, 0.f), r23 = make_float2(0.f, 0.f);
                    #pragma unroll 8
                    for (int m = half * 64; m < half * 64 + 64; ++m) {
                        float wm = s_w[e][m];
                        float2 wm2 = dup2(wm);
                        uint2 u = *(uint2*)(Mw + m * WORDN);
                        __half2* hp = (__half2*)&u;
                        float2 m01 = __half22float2(hp[0]);
                        float2 m23 = __half22float2(hp[1]);
                        ffma2(r01, wm2, m01);
                        ffma2(r23, wm2, m23);
                        float2 f01 = make_float2(1.f, 1.f), f23 = make_float2(1.f, 1.f);
                        ffma2(f01, wm2, e01);            // 1 - wm*e
                        ffma2(f23, wm2, e23);
                        float2 w01 = make_float2(0.f, 0.f), w23 = make_float2(0.f, 0.f);
                        ffma2(w01, wm2, a01);            // wm*a
                        ffma2(w23, wm2, a23);
                        ffma2(w01, m01, f01);            // m*(1-wm*e) + wm*a
                        ffma2(w23, m23, f23);
                        hp[0] = __floats2half2_rn(w01.x, w01.y);
                        hp[1] = __floats2half2_rn(w23.x, w23.y);
                        *(uint2*)(Mw + m * WORDN) = u;
                    }
                    *(float4*)&s_racc[e][half][lane * 4] =
                        make_float4(r01.x, r01.y, r23.x, r23.y);
                }
                BARN(1 + e, 64);
                // ---- combine read halves -> s_in rows 64.. ----
                {
                    int w = half * 32 + lane;
                    s_in[64 + w][e] = s_racc[e][0][w] + s_racc[e][1][w];
                    int w2 = w + 64;
                    s_in[64 + w2][e] = s_racc[e][0][w2] + s_racc[e][1][w2];
                }
            }
        }
        __syncthreads();   // B4: join
    }

    // ---- epilogue ----
    for (int q = tid; q < BN; q += 768) {
        int u = unsort_idxs[q];
        if (u >= b0 && u < b0 + 4) s_dst[u - b0] = q;
    }
    __syncthreads();
    if (tid < 256) {
        #pragma unroll
        for (int e = 0; e < 4; e++)
            out[(size_t)s_dst[e] * CTRLN + tid] = s_h[tid][e];
    }
    if (tid < 512) {
        int e = tid >> 7, w = tid & 127;
        out[(size_t)BN * CTRLN + (size_t)s_dst[e] * WORDN + w] = s_in[64 + w][e];
    }
}

// ---------------- launch ----------------
extern "C" void kernel_launch(void* const* d_in, const int* in_sizes, int n_in,
                              void* d_out, int out_size) {
    const float* data        = (const float*)d_in[0];
    const int*   batch_sizes = (const int*)d_in[1];
    const int*   unsort      = (const int*)d_in[2];
    const float* W_ih        = (const float*)d_in[3];
    const float* b_ih        = (const float*)d_in[4];
    const float* W_hh        = (const float*)d_in[5];
    const float* b_hh        = (const float*)d_in[6];
    const float* W_key       = (const float*)d_in[7];
    const float* b_key       = (const float*)d_in[8];
    const float* W_beta      = (const float*)d_in[9];
    const float* b_beta      = (const float*)d_in[10];
    const float* W_erase     = (const float*)d_in[11];
    const float* b_erase     = (const float*)d_in[12];
    const float* W_add       = (const float*)d_in[13];
    const float* b_add       = (const float*)d_in[14];
    const float* M0          = (const float*)d_in[15];

    cudaFuncSetAttribute(ntm_main, cudaFuncAttributeMaxDynamicSharedMemorySize, SMEM_TOTAL);
    ntm_prep<<<256, 256>>>(W_ih, W_hh, W_key, W_beta, W_erase, W_add);
    ntm_main<<<128, 768, SMEM_TOTAL>>>(data, batch_sizes, unsort,
                                       b_ih, b_hh, b_key, b_beta, b_erase, b_add,
                                       M0, (float*)d_out);
}

// round 8
// speedup vs baseline: 1.2104x; 1.2104x over previous
#include <cuda_runtime.h>
#include <cuda_fp16.h>
#include <math.h>

// Problem constants
#define CTRLN 256
#define WORDN 128
#define MEMN  128
#define DINN  64
#define BN    512
#define TN    512
#define GINN  192            // D_IN + WORD
#define EPSF  1e-6f

// ---------------- device scratch (static, no allocs) ----------------
__device__ __half g_WIH[24 * 768 * 8];    // [k8][o(768)][p(8)] halves, k = 8*k8+p
__device__ __half g_WHH[32 * 768 * 8];
__device__ __half g_WHD[32 * 512 * 8];    // head: key|erase|add|beta|pad

// ---------------- helpers ----------------
__device__ __forceinline__ void ffma2(float2 &d, float2 a, float2 b) {
    unsigned long long &du = reinterpret_cast<unsigned long long &>(d);
    unsigned long long au = reinterpret_cast<unsigned long long &>(a);
    unsigned long long bu = reinterpret_cast<unsigned long long &>(b);
    asm("fma.rn.f32x2 %0, %1, %2, %0;" : "+l"(du) : "l"(au), "l"(bu));
}
__device__ __forceinline__ float2 dup2(float a) { return make_float2(a, a); }
__device__ __forceinline__ float sigf(float x) {
    return __fdividef(1.0f, 1.0f + __expf(-x));
}
__device__ __forceinline__ float tanhf_fast(float x) {
    float ax = fabsf(x);
    float t = __expf(-2.0f * ax);
    float r = (1.0f - t) * __fdividef(1.0f, 1.0f + t);
    return copysignf(r, x);
}
__device__ __forceinline__ float softplusf(float x) {
    return fmaxf(x, 0.0f) + log1pf(__expf(-fabsf(x)));
}
__device__ __forceinline__ float sqrt_fast(float x) {
    float xs = x + 1e-30f;
    return xs * rsqrtf(xs);
}
#define BARN(id, cnt) asm volatile("bar.sync %0, %1;" :: "r"(id), "r"(cnt) : "memory")

// ---------------- K0: weight repack to fp16 ----------------
__global__ void ntm_prep(const float* __restrict__ W_ih, const float* __restrict__ W_hh,
                         const float* __restrict__ W_key, const float* __restrict__ W_beta,
                         const float* __restrict__ W_erase, const float* __restrict__ W_add) {
    int stride = gridDim.x * blockDim.x;
    int idx0 = blockIdx.x * blockDim.x + threadIdx.x;
    for (int i = idx0; i < 768 * 192; i += stride) {
        int o = i / 192, k = i % 192;
        g_WIH[((k >> 3) * 768 + o) * 8 + (k & 7)] = __float2half(W_ih[i]);
    }
    for (int i = idx0; i < 768 * 256; i += stride) {
        int o = i / 256, k = i % 256;
        g_WHH[((k >> 3) * 768 + o) * 8 + (k & 7)] = __float2half(W_hh[i]);
    }
    for (int i = idx0; i < 32 * 512 * 8; i += stride) {
        int k8 = i / (512 * 8);
        int r = i % (512 * 8);
        int o = r >> 3, p = r & 7;
        int k = k8 * 8 + p;
        float v = 0.0f;
        if (o < 128)       v = W_key[o * 256 + k];
        else if (o < 256)  v = W_erase[(o - 128) * 256 + k];
        else if (o < 384)  v = W_add[(o - 256) * 256 + k];
        else if (o == 384) v = W_beta[k];
        g_WHD[i] = __float2half(v);
    }
}

// ---------------- GEMV_P: gh (K=256) + gi_x (K=64) for output j, 4 elems ----------------
__device__ __forceinline__ void gemv_P(int j, float bR, float bZ, float bNi, float bNh,
                                       const float (*s_in)[4], const float (*s_h)[4],
                                       float (*s_redB)[256]) {
    float2 ar0 = dup2(bR), ar1 = dup2(bR);
    float2 az0 = dup2(bZ), az1 = dup2(bZ);
    float2 ai0 = dup2(bNi), ai1 = dup2(bNi);
    float2 ah0 = dup2(bNh), ah1 = dup2(bNh);
    {   // gi_x: k8 0..7 over x rows of s_in
        const uint4* W = (const uint4*)g_WIH;
        #pragma unroll 8
        for (int k8 = 0; k8 < 8; ++k8) {
            uint4 uwr = __ldg(&W[k8 * 768 + j]);
            uint4 uwz = __ldg(&W[k8 * 768 + 256 + j]);
            uint4 uwn = __ldg(&W[k8 * 768 + 512 + j]);
            const __half2* hr = (const __half2*)&uwr;
            const __half2* hz = (const __half2*)&uwz;
            const __half2* hn = (const __half2*)&uwn;
            #pragma unroll
            for (int q = 0; q < 4; ++q) {
                float2 wr2 = __half22float2(hr[q]);
                float2 wz2 = __half22float2(hz[q]);
                float2 wn2 = __half22float2(hn[q]);
                float4 ia = *(const float4*)&s_in[k8 * 8 + 2 * q][0];
                float4 ib = *(const float4*)&s_in[k8 * 8 + 2 * q + 1][0];
                float2 a01 = make_float2(ia.x, ia.y), a23 = make_float2(ia.z, ia.w);
                float2 b01 = make_float2(ib.x, ib.y), b23 = make_float2(ib.z, ib.w);
                ffma2(ar0, dup2(wr2.x), a01); ffma2(ar1, dup2(wr2.x), a23);
                ffma2(az0, dup2(wz2.x), a01); ffma2(az1, dup2(wz2.x), a23);
                ffma2(ai0, dup2(wn2.x), a01); ffma2(ai1, dup2(wn2.x), a23);
                ffma2(ar0, dup2(wr2.y), b01); ffma2(ar1, dup2(wr2.y), b23);
                ffma2(az0, dup2(wz2.y), b01); ffma2(az1, dup2(wz2.y), b23);
                ffma2(ai0, dup2(wn2.y), b01); ffma2(ai1, dup2(wn2.y), b23);
            }
        }
    }
    {   // gh: k8 0..31 over s_h
        const uint4* W = (const uint4*)g_WHH;
        #pragma unroll 8
        for (int k8 = 0; k8 < 32; ++k8) {
            uint4 uwr = __ldg(&W[k8 * 768 + j]);
            uint4 uwz = __ldg(&W[k8 * 768 + 256 + j]);
            uint4 uwn = __ldg(&W[k8 * 768 + 512 + j]);
            const __half2* hr = (const __half2*)&uwr;
            const __half2* hz = (const __half2*)&uwz;
            const __half2* hn = (const __half2*)&uwn;
            #pragma unroll
            for (int q = 0; q < 4; ++q) {
                float2 wr2 = __half22float2(hr[q]);
                float2 wz2 = __half22float2(hz[q]);
                float2 wn2 = __half22float2(hn[q]);
                float4 ia = *(const float4*)&s_h[k8 * 8 + 2 * q][0];
                float4 ib = *(const float4*)&s_h[k8 * 8 + 2 * q + 1][0];
                float2 a01 = make_float2(ia.x, ia.y), a23 = make_float2(ia.z, ia.w);
                float2 b01 = make_float2(ib.x, ib.y), b23 = make_float2(ib.z, ib.w);
                ffma2(ar0, dup2(wr2.x), a01); ffma2(ar1, dup2(wr2.x), a23);
                ffma2(az0, dup2(wz2.x), a01); ffma2(az1, dup2(wz2.x), a23);
                ffma2(ah0, dup2(wn2.x), a01); ffma2(ah1, dup2(wn2.x), a23);
                ffma2(ar0, dup2(wr2.y), b01); ffma2(ar1, dup2(wr2.y), b23);
                ffma2(az0, dup2(wz2.y), b01); ffma2(az1, dup2(wz2.y), b23);
                ffma2(ah0, dup2(wn2.y), b01); ffma2(ah1, dup2(wn2.y), b23);
            }
        }
    }
    s_redB[0][j] = ar0.x;  s_redB[1][j] = ar0.y;  s_redB[2][j] = ar1.x;  s_redB[3][j] = ar1.y;
    s_redB[4][j] = az0.x;  s_redB[5][j] = az0.y;  s_redB[6][j] = az1.x;  s_redB[7][j] = az1.y;
    s_redB[8][j] = ai0.x;  s_redB[9][j] = ai0.y;  s_redB[10][j] = ai1.x; s_redB[11][j] = ai1.y;
    s_redB[12][j] = ah0.x; s_redB[13][j] = ah0.y; s_redB[14][j] = ah1.x; s_redB[15][j] = ah1.y;
}

#define SMEM_TOTAL (52288 + 4 * MEMN * WORDN * 2)   // 183360 bytes

// ---------------- K1: persistent pipelined kernel, M in SMEM ----------------
__global__ __launch_bounds__(512, 1)
void ntm_main(const float* __restrict__ data, const int* __restrict__ batch_sizes,
              const int* __restrict__ unsort_idxs,
              const float* __restrict__ b_ih, const float* __restrict__ b_hh,
              const float* __restrict__ b_key, const float* __restrict__ b_beta,
              const float* __restrict__ b_erase, const float* __restrict__ b_add,
              const float* __restrict__ M0, float* __restrict__ out) {
    extern __shared__ __align__(16) unsigned char dsm[];
    float (*s_in)[4]        = (float(*)[4])(dsm);              // [192][4]
    float (*s_h)[4]         = (float(*)[4])(dsm + 3072);       // [256][4]
    float (*s_redA)[256]    = (float(*)[256])(dsm + 7168);     // [12][256]
    float (*s_redB)[256]    = (float(*)[256])(dsm + 19456);    // [16][256]
    float (*s_key)[128]     = (float(*)[128])(dsm + 35840);    // [4][128]
    float (*s_e)[128]       = (float(*)[128])(dsm + 37888);
    float (*s_a)[128]       = (float(*)[128])(dsm + 39936);
    float (*s_w)[128]       = (float(*)[128])(dsm + 41984);
    float (*s_racc)[4][128] = (float(*)[4][128])(dsm + 44032); // [4][4][128] = 8KB
    float* s_beta           = (float*)(dsm + 52224);
    int*   s_len            = (int*)(dsm + 52240);
    int*   s_dst            = (int*)(dsm + 52256);
    __half* s_M             = (__half*)(dsm + 52288);          // [4][128][128] fp16

    const int tid = threadIdx.x;
    const int lane = tid & 31;
    const int warp = tid >> 5;
    const int b0 = blockIdx.x * 4;
    const int j = tid & 255;
    const int sk = tid >> 8;     // 0 = MEM warps (0-7), 1 = GEMV warps (8-15)

    // ---- active lengths ----
    if (warp < 4) {
        int e = warp, cnt = 0;
        for (int t = lane; t < TN; t += 32) cnt += (batch_sizes[t] > (b0 + e)) ? 1 : 0;
        #pragma unroll
        for (int s = 16; s; s >>= 1) cnt += __shfl_xor_sync(0xffffffffu, cnt, s);
        if (lane == 0) s_len[e] = cnt;
    }
    // ---- init M in SMEM from M0 (fp32 -> fp16), 4 copies ----
    for (int i = tid; i < (MEMN * WORDN) / 2; i += 512) {
        float2 f = ((const float2*)M0)[i];
        __half2 h = __floats2half2_rn(f.x, f.y);
        #pragma unroll
        for (int e = 0; e < 4; e++)
            ((__half2*)s_M)[e * ((MEMN * WORDN) / 2) + i] = h;
    }
    for (int i = tid; i < GINN * 4; i += 512) (&s_in[0][0])[i] = 0.0f;
    for (int i = tid; i < CTRLN * 4; i += 512) (&s_h[0][0])[i] = 0.0f;
    for (int i = tid; i < 16 * 256; i += 512) (&s_redB[0][0])[i] = 0.0f;

    // ---- biases ----
    float bR = 0.f, bZ = 0.f, bNi = 0.f, bNh = 0.f;   // GEMV warps
    if (sk == 1) {
        bR = b_ih[j] + b_hh[j];
        bZ = b_ih[256 + j] + b_hh[256 + j];
        bNi = b_ih[512 + j];
        bNh = b_hh[512 + j];
    }
    float bH1 = 0.f, bH2 = 0.f;                       // MEM warps (head outputs tid, 256+tid)
    if (sk == 0) {
        bH1 = (tid < 128) ? b_key[tid] : b_erase[tid - 128];
        bH2 = (tid < 128) ? b_add[tid] : ((tid == 128) ? b_beta[0] : 0.0f);
    }

    // ---- module role: 4 warps per elem (2 MEM + 2 GEMV) ----
    const int me = (warp < 8) ? (warp >> 1) : ((warp >> 1) - 4);
    const int qt = (warp < 8) ? (warp & 1) : (2 + (warp & 1));

    // ---- x prefetch prologue ----
    const int xe = tid >> 6, xd = tid & 63;           // valid for tid<256
    float xreg = 0.f;
    if (tid < 256) xreg = data[((size_t)0 * BN + (b0 + xe)) * DINN + xd];   // x_0
    __syncthreads();

    const int L0 = s_len[0], L1 = s_len[1], L2 = s_len[2], L3 = s_len[3];
    const int Tmax = max(max(L0, L1), max(L2, L3));

    if (tid < 256) {
        s_in[xd][xe] = xreg;                                                // x_0 -> smem
        xreg = data[((size_t)1 * BN + (b0 + xe)) * DINN + xd];              // x_1 -> reg
    }
    __syncthreads();
    // prologue pipelined GEMV: P_0 = gh(h=0) + gi_x(x_0) + biases
    if (sk == 1) gemv_P(j, bR, bZ, bNi, bNh, s_in, s_h, s_redB);
    __syncthreads();

    for (int t = 0; t < Tmax; ++t) {
        // ============ SERIAL: gi_read (K=128, rows 64-191), split-K 2 ways ============
        float2 gr0 = make_float2(0.f, 0.f), gr1 = make_float2(0.f, 0.f);
        float2 gz0 = make_float2(0.f, 0.f), gz1 = make_float2(0.f, 0.f);
        float2 gi0 = make_float2(0.f, 0.f), gi1 = make_float2(0.f, 0.f);
        {
            const uint4* W = (const uint4*)g_WIH;
            #pragma unroll 8
            for (int k8 = 8 + sk * 8; k8 < 16 + sk * 8; ++k8) {
                uint4 uwr = __ldg(&W[k8 * 768 + j]);
                uint4 uwz = __ldg(&W[k8 * 768 + 256 + j]);
                uint4 uwn = __ldg(&W[k8 * 768 + 512 + j]);
                const __half2* hr = (const __half2*)&uwr;
                const __half2* hz = (const __half2*)&uwz;
                const __half2* hn = (const __half2*)&uwn;
                #pragma unroll
                for (int q = 0; q < 4; ++q) {
                    float2 wr2 = __half22float2(hr[q]);
                    float2 wz2 = __half22float2(hz[q]);
                    float2 wn2 = __half22float2(hn[q]);
                    float4 ia = *(const float4*)&s_in[k8 * 8 + 2 * q][0];
                    float4 ib = *(const float4*)&s_in[k8 * 8 + 2 * q + 1][0];
                    float2 a01 = make_float2(ia.x, ia.y), a23 = make_float2(ia.z, ia.w);
                    float2 b01 = make_float2(ib.x, ib.y), b23 = make_float2(ib.z, ib.w);
                    ffma2(gr0, dup2(wr2.x), a01); ffma2(gr1, dup2(wr2.x), a23);
                    ffma2(gz0, dup2(wz2.x), a01); ffma2(gz1, dup2(wz2.x), a23);
                    ffma2(gi0, dup2(wn2.x), a01); ffma2(gi1, dup2(wn2.x), a23);
                    ffma2(gr0, dup2(wr2.y), b01); ffma2(gr1, dup2(wr2.y), b23);
                    ffma2(gz0, dup2(wz2.y), b01); ffma2(gz1, dup2(wz2.y), b23);
                    ffma2(gi0, dup2(wn2.y), b01); ffma2(gi1, dup2(wn2.y), b23);
                }
            }
        }
        if (sk == 1) {
            s_redA[0][j] = gr0.x;  s_redA[1][j] = gr0.y;  s_redA[2][j] = gr1.x;  s_redA[3][j] = gr1.y;
            s_redA[4][j] = gz0.x;  s_redA[5][j] = gz0.y;  s_redA[6][j] = gz1.x;  s_redA[7][j] = gz1.y;
            s_redA[8][j] = gi0.x;  s_redA[9][j] = gi0.y;  s_redA[10][j] = gi1.x; s_redA[11][j] = gi1.y;
        }
        __syncthreads();   // B1

        // ---- combine + gates + x-store (MEM warps own both) ----
        if (sk == 0) {
            float pr[4] = {gr0.x, gr0.y, gr1.x, gr1.y};
            float pz[4] = {gz0.x, gz0.y, gz1.x, gz1.y};
            float pi[4] = {gi0.x, gi0.y, gi1.x, gi1.y};
            float4 hold = *(const float4*)&s_h[j][0];
            float ho[4] = {hold.x, hold.y, hold.z, hold.w};
            float hn_[4];
            #pragma unroll
            for (int e = 0; e < 4; e++) {
                float ppr = pr[e] + s_redA[e][j] + s_redB[e][j];
                float ppz = pz[e] + s_redA[4 + e][j] + s_redB[4 + e][j];
                float ppi = pi[e] + s_redA[8 + e][j] + s_redB[8 + e][j];
                float pph = s_redB[12 + e][j];
                float r = sigf(ppr);
                float z = sigf(ppz);
                float n = tanhf_fast(ppi + r * pph);
                hn_[e] = (1.0f - z) * n + z * ho[e];
            }
            if (t < L0) s_h[j][0] = hn_[0];
            if (t < L1) s_h[j][1] = hn_[1];
            if (t < L2) s_h[j][2] = hn_[2];
            if (t < L3) s_h[j][3] = hn_[3];
            // x_{t+1} -> smem, prefetch x_{t+2}
            s_in[xd][xe] = xreg;
            int tn = min(t + 2, TN - 1);
            xreg = data[((size_t)tn * BN + (b0 + xe)) * DINN + xd];
        }
        __syncthreads();   // B2: h_t and x_{t+1} ready

        // ============ PARALLEL SEGMENT ============
        if (sk == 1) {
            // GEMV warps: P_{t+1} = gh(h_t) + gi_x(x_{t+1}) + biases
            gemv_P(j, bR, bZ, bNi, bNh, s_in, s_h, s_redB);
        } else {
            // ---- MEM warps: head GEMV (outputs tid, 256+tid; K=256) ----
            float2 h10 = dup2(bH1), h11 = dup2(bH1);
            float2 h20 = dup2(bH2), h21 = dup2(bH2);
            {
                const uint4* W = (const uint4*)g_WHD;
                #pragma unroll 8
                for (int k8 = 0; k8 < 32; ++k8) {
                    uint4 uw1 = __ldg(&W[k8 * 512 + tid]);
                    uint4 uw2 = __ldg(&W[k8 * 512 + 256 + tid]);
                    const __half2* h1p = (const __half2*)&uw1;
                    const __half2* h2p = (const __half2*)&uw2;
                    #pragma unroll
                    for (int q = 0; q < 4; ++q) {
                        float2 w12 = __half22float2(h1p[q]);
                        float2 w22 = __half22float2(h2p[q]);
                        float4 ia = *(const float4*)&s_h[k8 * 8 + 2 * q][0];
                        float4 ib = *(const float4*)&s_h[k8 * 8 + 2 * q + 1][0];
                        float2 a01 = make_float2(ia.x, ia.y), a23 = make_float2(ia.z, ia.w);
                        float2 b01 = make_float2(ib.x, ib.y), b23 = make_float2(ib.z, ib.w);
                        ffma2(h10, dup2(w12.x), a01); ffma2(h11, dup2(w12.x), a23);
                        ffma2(h20, dup2(w22.x), a01); ffma2(h21, dup2(w22.x), a23);
                        ffma2(h10, dup2(w12.y), b01); ffma2(h11, dup2(w12.y), b23);
                        ffma2(h20, dup2(w22.y), b01); ffma2(h21, dup2(w22.y), b23);
                    }
                }
            }
            {
                float v1[4] = {h10.x, h10.y, h11.x, h11.y};
                float v2[4] = {h20.x, h20.y, h21.x, h21.y};
                #pragma unroll
                for (int e = 0; e < 4; e++) {
                    if (tid < 128) {
                        s_key[e][tid] = tanhf_fast(v1[e]);   // raw key
                        s_a[e][tid] = v2[e];
                    } else {
                        s_e[e][tid - 128] = sigf(v1[e]);
                        if (tid == 128) s_beta[e] = softplusf(v2[e]);
                    }
                }
            }
            BARN(5, 256);   // all head outputs visible to all MEM warps
        }

        // ============ MEMORY MODULE: 4 warps per elem (2 MEM + 2 GEMV) ============
        {
            const int e = me;
            if (t < s_len[e]) {
                BARN(1 + e, 128);   // join: head outputs visible, gemv_P done
                // ---- pass 1: dot(M, k_raw)/(||M||+eps), M from SMEM, 32 rows/warp ----
                const __half* Me = s_M + e * (MEMN * WORDN);
                {
                    int rl = lane >> 3;
                    int cc = (lane & 7) * 16;
                    float2 kx[8];
                    #pragma unroll
                    for (int i = 0; i < 8; i++)
                        kx[i] = make_float2(s_key[e][cc + 2 * i], s_key[e][cc + 2 * i + 1]);
                    #pragma unroll 4
                    for (int mb = qt * 32; mb < qt * 32 + 32; mb += 4) {
                        int m = mb + rl;
                        const uint4* Mr = (const uint4*)(Me + m * WORDN + cc);
                        uint4 u0 = Mr[0];
                        uint4 u1 = Mr[1];
                        const __half2* p0 = (const __half2*)&u0;
                        const __half2* p1 = (const __half2*)&u1;
                        float2 d2 = make_float2(0.f, 0.f), n2 = make_float2(0.f, 0.f);
                        #pragma unroll
                        for (int q = 0; q < 4; q++) {
                            float2 f0 = __half22float2(p0[q]);
                            float2 f1 = __half22float2(p1[q]);
                            ffma2(d2, f0, kx[q]);
                            ffma2(n2, f0, f0);
                            ffma2(d2, f1, kx[4 + q]);
                            ffma2(n2, f1, f1);
                        }
                        float dot = d2.x + d2.y, nrm = n2.x + n2.y;
                        #pragma unroll
                        for (int s = 1; s < 8; s <<= 1) {
                            dot += __shfl_xor_sync(0xffffffffu, dot, s);
                            nrm += __shfl_xor_sync(0xffffffffu, nrm, s);
                        }
                        if ((lane & 7) == 0) s_w[e][m] = __fdividef(dot, sqrt_fast(nrm) + EPSF);
                    }
                }
                BARN(1 + e, 128);
                // ---- softmax (qt==0 warp): scale = beta / (||k||+eps) ----
                if (qt == 0) {
                    float q0 = s_key[e][lane];
                    float q1 = s_key[e][lane + 32];
                    float q2 = s_key[e][lane + 64];
                    float q3 = s_key[e][lane + 96];
                    float ss = q0 * q0 + q1 * q1 + q2 * q2 + q3 * q3;
                    #pragma unroll
                    for (int s = 16; s; s >>= 1) ss += __shfl_xor_sync(0xffffffffu, ss, s);
                    float scale = __fdividef(s_beta[e], sqrt_fast(ss) + EPSF);
                    float v0 = scale * s_w[e][lane];
                    float v1 = scale * s_w[e][lane + 32];
                    float v2 = scale * s_w[e][lane + 64];
                    float v3 = scale * s_w[e][lane + 96];
                    float mx = fmaxf(fmaxf(v0, v1), fmaxf(v2, v3));
                    #pragma unroll
                    for (int s = 16; s; s >>= 1) mx = fmaxf(mx, __shfl_xor_sync(0xffffffffu, mx, s));
                    v0 = __expf(v0 - mx); v1 = __expf(v1 - mx);
                    v2 = __expf(v2 - mx); v3 = __expf(v3 - mx);
                    float sum = v0 + v1 + v2 + v3;
                    #pragma unroll
                    for (int s = 16; s; s >>= 1) sum += __shfl_xor_sync(0xffffffffu, sum, s);
                    float inv = __fdividef(1.0f, sum);
                    s_w[e][lane] = v0 * inv;
                    s_w[e][lane + 32] = v1 * inv;
                    s_w[e][lane + 64] = v2 * inv;
                    s_w[e][lane + 96] = v3 * inv;
                }
                BARN(1 + e, 128);
                // ---- pass 2: read + M update, all in SMEM, f32x2 math, 32 rows/warp ----
                {
                    __half* Mw = s_M + e * (MEMN * WORDN) + lane * 4;
                    float4 e4 = *(const float4*)&s_e[e][lane * 4];
                    float4 a4 = *(const float4*)&s_a[e][lane * 4];
                    float2 e01 = make_float2(-e4.x, -e4.y), e23 = make_float2(-e4.z, -e4.w);
                    float2 a01 = make_float2(a4.x, a4.y),   a23 = make_float2(a4.z, a4.w);
                    float2 r01 = make_float2(0.f, 0.f), r23 = make_float2(0.f, 0.f);
                    #pragma unroll 8
                    for (int m = qt * 32; m < qt * 32 + 32; ++m) {
                        float wm = s_w[e][m];
                        float2 wm2 = dup2(wm);
                        uint2 u = *(uint2*)(Mw + m * WORDN);
                        __half2* hp = (__half2*)&u;
                        float2 m01 = __half22float2(hp[0]);
                        float2 m23 = __half22float2(hp[1]);
                        ffma2(r01, wm2, m01);
                        ffma2(r23, wm2, m23);
                        float2 f01 = make_float2(1.f, 1.f), f23 = make_float2(1.f, 1.f);
                        ffma2(f01, wm2, e01);            // 1 - wm*e
                        ffma2(f23, wm2, e23);
                        float2 w01 = make_float2(0.f, 0.f), w23 = make_float2(0.f, 0.f);
                        ffma2(w01, wm2, a01);            // wm*a
                        ffma2(w23, wm2, a23);
                        ffma2(w01, m01, f01);            // m*(1-wm*e) + wm*a
                        ffma2(w23, m23, f23);
                        hp[0] = __floats2half2_rn(w01.x, w01.y);
                        hp[1] = __floats2half2_rn(w23.x, w23.y);
                        *(uint2*)(Mw + m * WORDN) = u;
                    }
                    *(float4*)&s_racc[e][qt][lane * 4] =
                        make_float4(r01.x, r01.y, r23.x, r23.y);
                }
                BARN(1 + e, 128);
                // ---- combine read quarters -> s_in rows 64.. (128 threads, 1 word each) ----
                {
                    int w = qt * 32 + lane;
                    s_in[64 + w][e] = (s_racc[e][0][w] + s_racc[e][1][w])
                                    + (s_racc[e][2][w] + s_racc[e][3][w]);
                }
            }
        }
        __syncthreads();   // B4: join
    }

    // ---- epilogue ----
    for (int q = tid; q < BN; q += 512) {
        int u = unsort_idxs[q];
        if (u >= b0 && u < b0 + 4) s_dst[u - b0] = q;
    }
    __syncthreads();
    if (tid < 256) {
        #pragma unroll
        for (int e = 0; e < 4; e++)
            out[(size_t)s_dst[e] * CTRLN + tid] = s_h[tid][e];
    }
    {
        int e = tid >> 7, w = tid & 127;
        if (tid < 512)
            out[(size_t)BN * CTRLN + (size_t)s_dst[e] * WORDN + w] = s_in[64 + w][e];
    }
}

// ---------------- launch ----------------
extern "C" void kernel_launch(void* const* d_in, const int* in_sizes, int n_in,
                              void* d_out, int out_size) {
    const float* data        = (const float*)d_in[0];
    const int*   batch_sizes = (const int*)d_in[1];
    const int*   unsort      = (const int*)d_in[2];
    const float* W_ih        = (const float*)d_in[3];
    const float* b_ih        = (const float*)d_in[4];
    const float* W_hh        = (const float*)d_in[5];
    const float* b_hh        = (const float*)d_in[6];
    const float* W_key       = (const float*)d_in[7];
    const float* b_key       = (const float*)d_in[8];
    const float* W_beta      = (const float*)d_in[9];
    const float* b_beta      = (const float*)d_in[10];
    const float* W_erase     = (const float*)d_in[11];
    const float* b_erase     = (const float*)d_in[12];
    const float* W_add       = (const float*)d_in[13];
    const float* b_add       = (const float*)d_in[14];
    const float* M0          = (const float*)d_in[15];

    cudaFuncSetAttribute(ntm_main, cudaFuncAttributeMaxDynamicSharedMemorySize, SMEM_TOTAL);
    ntm_prep<<<256, 256>>>(W_ih, W_hh, W_key, W_beta, W_erase, W_add);
    ntm_main<<<128, 512, SMEM_TOTAL>>>(data, batch_sizes, unsort,
                                       b_ih, b_hh, b_key, b_beta, b_erase, b_add,
                                       M0, (float*)d_out);
}